// round 6
// baseline (speedup 1.0000x reference)
#include <cuda_runtime.h>

#define N_NODES 100000
#define DIM 64
#define N_EDGES 1250000
#define CAP 64          // bucket slots per node; Poisson(12.5) max degree ~40

// Static scratch (no runtime allocation).
__device__ int g_cnt[N_NODES];                    // incoming-edge count per node
__device__ int g_bucket[(size_t)N_NODES * CAP];   // src ids, bucketed by dst
__device__ int g_novf;                            // overflow edge count (normally 0)
__device__ int g_ovf_src[N_EDGES];                // overflow edges (correctness path)
__device__ int g_ovf_dst[N_EDGES];

__global__ void zero_kernel() {
    int i = blockIdx.x * blockDim.x + threadIdx.x;
    int4 z = make_int4(0, 0, 0, 0);
    if (i < N_NODES / 4) reinterpret_cast<int4*>(g_cnt)[i] = z;
    if (i == 0) g_novf = 0;
}

// 4 edges per thread (int4 loads): claim slots in dst buckets.
__global__ void fill_kernel(const int* __restrict__ edge_index) {
    int t = blockIdx.x * blockDim.x + threadIdx.x;
    if (t >= N_EDGES / 4) return;
    int4 s4 = reinterpret_cast<const int4*>(edge_index)[t];
    int4 d4 = reinterpret_cast<const int4*>(edge_index + N_EDGES)[t];
    int ss[4] = {s4.x, s4.y, s4.z, s4.w};
    int dd[4] = {d4.x, d4.y, d4.z, d4.w};
    #pragma unroll
    for (int k = 0; k < 4; k++) {
        int src = ss[k], dst = dd[k];
        int slot = atomicAdd(&g_cnt[dst], 1);
        if (slot < CAP) {
            g_bucket[(size_t)dst * CAP + slot] = src;
        } else {
            int q = atomicAdd(&g_novf, 1);
            if (q < N_EDGES) { g_ovf_src[q] = src; g_ovf_dst[q] = dst; }
        }
    }
}

// Two nodes per warp (16 lanes each, float4 per lane = full 256B row).
__global__ void pull_kernel(const float* __restrict__ x,
                            float* __restrict__ out) {
    int gtid = blockIdx.x * blockDim.x + threadIdx.x;
    int warp = gtid >> 5;
    int lane = gtid & 31;
    int group = lane >> 4;       // 0 or 1: which node this half-warp serves
    int gl = lane & 15;          // lane within the 16-lane group
    int node = warp * 2 + group; // N_NODES even: warps fully valid or fully idle
    if (node >= N_NODES) return;

    const unsigned FULL = 0xFFFFFFFFu;
    int gbase = group << 4;

    int cnt = g_cnt[node];
    int m = cnt < CAP ? cnt : CAP;
    int m_other = __shfl_xor_sync(FULL, m, 16);
    int mmax = m > m_other ? m : m_other;

    float4 acc = make_float4(0.f, 0.f, 0.f, 0.f);
    size_t base = (size_t)node * CAP;
    const float* xg = x + (size_t)gl * 4;   // this lane's 4 dims within any row

    for (int i = 0; i < mmax; i += 16) {
        int s = 0;
        if (i + gl < m) s = g_bucket[base + i + gl];
        int nmax = (mmax - i) < 16 ? (mmax - i) : 16;
        int nme = m - i;            // valid count for MY group this chunk

        int j = 0;
        for (; j + 4 <= nmax; j += 4) {
            int s0 = __shfl_sync(FULL, s, gbase + j + 0);
            int s1 = __shfl_sync(FULL, s, gbase + j + 1);
            int s2 = __shfl_sync(FULL, s, gbase + j + 2);
            int s3 = __shfl_sync(FULL, s, gbase + j + 3);
            int v = nme - j;        // uniform within group
            if (v >= 4) {
                float4 a0 = *reinterpret_cast<const float4*>(xg + (size_t)s0 * DIM);
                float4 a1 = *reinterpret_cast<const float4*>(xg + (size_t)s1 * DIM);
                float4 a2 = *reinterpret_cast<const float4*>(xg + (size_t)s2 * DIM);
                float4 a3 = *reinterpret_cast<const float4*>(xg + (size_t)s3 * DIM);
                acc.x += (a0.x + a1.x) + (a2.x + a3.x);
                acc.y += (a0.y + a1.y) + (a2.y + a3.y);
                acc.z += (a0.z + a1.z) + (a2.z + a3.z);
                acc.w += (a0.w + a1.w) + (a2.w + a3.w);
            } else if (v > 0) {
                int sv[4] = {s0, s1, s2, s3};
                for (int k = 0; k < v; k++) {
                    float4 a = *reinterpret_cast<const float4*>(xg + (size_t)sv[k] * DIM);
                    acc.x += a.x; acc.y += a.y; acc.z += a.z; acc.w += a.w;
                }
            }
        }
        for (; j < nmax; j++) {
            int sj = __shfl_sync(FULL, s, gbase + j);
            if (j < nme) {
                float4 a = *reinterpret_cast<const float4*>(xg + (size_t)sj * DIM);
                acc.x += a.x; acc.y += a.y; acc.z += a.z; acc.w += a.w;
            }
        }
    }

    // Overflow correctness path (normally dead: g_novf == 0).
    unsigned any_ovf = __ballot_sync(FULL, cnt > CAP);
    if (any_ovf) {
        int no = g_novf;
        if (no > N_EDGES) no = N_EDGES;
        int n0 = warp * 2, n1 = warp * 2 + 1;
        for (int i = 0; i < no; i += 32) {
            int d = -1, s = 0;
            if (i + lane < no) { d = g_ovf_dst[i + lane]; s = g_ovf_src[i + lane]; }
            unsigned mask = __ballot_sync(FULL, d == n0 || d == n1);
            while (mask) {
                int j = __ffs(mask) - 1;
                mask &= mask - 1;
                int sj = __shfl_sync(FULL, s, j);
                int dj = __shfl_sync(FULL, d, j);
                if (dj == node) {
                    float4 a = *reinterpret_cast<const float4*>(xg + (size_t)sj * DIM);
                    acc.x += a.x; acc.y += a.y; acc.z += a.z; acc.w += a.w;
                }
            }
        }
    }

    float inv_cnt = 1.0f / fmaxf((float)cnt, 1.0f);
    acc.x *= inv_cnt; acc.y *= inv_cnt; acc.z *= inv_cnt; acc.w *= inv_cnt;

    float ss = acc.x * acc.x + acc.y * acc.y + acc.z * acc.z + acc.w * acc.w;
    // Reduce within the 16-lane group (group bit is bit 4 — untouched).
    ss += __shfl_xor_sync(FULL, ss, 8);
    ss += __shfl_xor_sync(FULL, ss, 4);
    ss += __shfl_xor_sync(FULL, ss, 2);
    ss += __shfl_xor_sync(FULL, ss, 1);

    float scale = 2.0f / fmaxf(sqrtf(ss), 1e-12f);
    float4 r;
    r.x = fmaxf(acc.x * scale, 0.0f);
    r.y = fmaxf(acc.y * scale, 0.0f);
    r.z = fmaxf(acc.z * scale, 0.0f);
    r.w = fmaxf(acc.w * scale, 0.0f);
    reinterpret_cast<float4*>(out + (size_t)node * DIM)[gl] = r;
}

extern "C" void kernel_launch(void* const* d_in, const int* in_sizes, int n_in,
                              void* d_out, int out_size) {
    const float* x = (const float*)d_in[0];
    const int* edge_index = (const int*)d_in[1];
    // d_in[2] = edge_weights: unused by the reference computation.
    float* out = (float*)d_out;

    {
        int total = N_NODES / 4;
        int threads = 256;
        int blocks = (total + threads - 1) / threads;
        zero_kernel<<<blocks, threads>>>();
    }
    {
        int total = N_EDGES / 4;
        int threads = 256;
        int blocks = (total + threads - 1) / threads;
        fill_kernel<<<blocks, threads>>>(edge_index);
    }
    {
        long long total = (long long)(N_NODES / 2) * 32;  // 2 nodes per warp
        int threads = 256;
        int blocks = (int)((total + threads - 1) / threads);
        pull_kernel<<<blocks, threads>>>(x, out);
    }
}

// round 7
// speedup vs baseline: 1.3150x; 1.3150x over previous
#include <cuda_runtime.h>

#define N_NODES 100000
#define DIM 64
#define N_EDGES 1250000
#define CAP 64          // bucket slots per node; Poisson(12.5) max degree ~40

// Static scratch (zero-initialized at module load; pull re-zeroes g_cnt/g_novf
// after use so every graph replay starts from a clean state).
__device__ int g_cnt[N_NODES];                    // incoming-edge count per node
__device__ int g_bucket[(size_t)N_NODES * CAP];   // src ids, bucketed by dst
__device__ int g_novf;                            // overflow edge count (normally 0)
__device__ int g_ovf_src[N_EDGES];                // overflow edges (correctness path)
__device__ int g_ovf_dst[N_EDGES];

// 4 edges per thread (int4 loads): claim slots in dst buckets.
__global__ void fill_kernel(const int* __restrict__ edge_index) {
    int t = blockIdx.x * blockDim.x + threadIdx.x;
    if (t >= N_EDGES / 4) return;
    int4 s4 = reinterpret_cast<const int4*>(edge_index)[t];
    int4 d4 = reinterpret_cast<const int4*>(edge_index + N_EDGES)[t];
    int ss[4] = {s4.x, s4.y, s4.z, s4.w};
    int dd[4] = {d4.x, d4.y, d4.z, d4.w};
    #pragma unroll
    for (int k = 0; k < 4; k++) {
        int src = ss[k], dst = dd[k];
        int slot = atomicAdd(&g_cnt[dst], 1);
        if (slot < CAP) {
            g_bucket[(size_t)dst * CAP + slot] = src;
        } else {
            int q = atomicAdd(&g_novf, 1);
            if (q < N_EDGES) { g_ovf_src[q] = src; g_ovf_dst[q] = dst; }
        }
    }
}

// Warp per node: gather fp32 rows (float2/lane), 4 gathers in flight,
// mean + L2-normalize + x2 + relu; reset this node's counter for next replay.
__global__ void pull_kernel(const float* __restrict__ x,
                            float* __restrict__ out) {
    int gtid = blockIdx.x * blockDim.x + threadIdx.x;
    int node = gtid >> 5;
    int lane = gtid & 31;
    if (node >= N_NODES) return;

    const unsigned FULL = 0xFFFFFFFFu;
    int cnt = g_cnt[node];
    int m = cnt < CAP ? cnt : CAP;

    float accx = 0.f, accy = 0.f;
    size_t base = (size_t)node * CAP;
    const float2* xb = reinterpret_cast<const float2*>(x) + lane;  // lane's column

    for (int i = 0; i < m; i += 32) {
        int s = 0;
        if (i + lane < m) s = g_bucket[base + i + lane];
        int n = (m - i) < 32 ? (m - i) : 32;

        int j = 0;
        // 4 independent gathers in flight per warp.
        for (; j + 4 <= n; j += 4) {
            int s0 = __shfl_sync(FULL, s, j + 0);
            int s1 = __shfl_sync(FULL, s, j + 1);
            int s2 = __shfl_sync(FULL, s, j + 2);
            int s3 = __shfl_sync(FULL, s, j + 3);
            float2 v0 = xb[(size_t)s0 * (DIM / 2)];
            float2 v1 = xb[(size_t)s1 * (DIM / 2)];
            float2 v2 = xb[(size_t)s2 * (DIM / 2)];
            float2 v3 = xb[(size_t)s3 * (DIM / 2)];
            accx += (v0.x + v1.x) + (v2.x + v3.x);
            accy += (v0.y + v1.y) + (v2.y + v3.y);
        }
        for (; j < n; j++) {
            int sj = __shfl_sync(FULL, s, j);
            float2 v = xb[(size_t)sj * (DIM / 2)];
            accx += v.x;
            accy += v.y;
        }
    }

    // Overflow correctness path (normally dead: g_novf == 0).
    if (cnt > CAP) {
        int no = g_novf;
        if (no > N_EDGES) no = N_EDGES;
        for (int i = 0; i < no; i += 32) {
            int d = -1, s = 0;
            if (i + lane < no) { d = g_ovf_dst[i + lane]; s = g_ovf_src[i + lane]; }
            unsigned mask = __ballot_sync(FULL, d == node);
            while (mask) {
                int j = __ffs(mask) - 1;
                mask &= mask - 1;
                int sj = __shfl_sync(FULL, s, j);
                float2 v = xb[(size_t)sj * (DIM / 2)];
                accx += v.x;
                accy += v.y;
            }
        }
    }

    // Reset state for the next graph replay (exclusive owner of this element).
    if (lane == 0) g_cnt[node] = 0;
    if (node == 0 && lane == 1) g_novf = 0;

    float inv_cnt = 1.0f / fmaxf((float)cnt, 1.0f);
    accx *= inv_cnt;
    accy *= inv_cnt;

    float ss = accx * accx + accy * accy;
    #pragma unroll
    for (int off = 16; off > 0; off >>= 1)
        ss += __shfl_xor_sync(FULL, ss, off);

    float scale = 2.0f / fmaxf(sqrtf(ss), 1e-12f);
    float2 r;
    r.x = fmaxf(accx * scale, 0.0f);
    r.y = fmaxf(accy * scale, 0.0f);
    reinterpret_cast<float2*>(out + (size_t)node * DIM)[lane] = r;
}

extern "C" void kernel_launch(void* const* d_in, const int* in_sizes, int n_in,
                              void* d_out, int out_size) {
    const float* x = (const float*)d_in[0];
    const int* edge_index = (const int*)d_in[1];
    // d_in[2] = edge_weights: unused by the reference computation.
    float* out = (float*)d_out;

    {
        int total = N_EDGES / 4;
        int threads = 256;
        int blocks = (total + threads - 1) / threads;
        fill_kernel<<<blocks, threads>>>(edge_index);
    }
    {
        long long total = (long long)N_NODES * 32;
        int threads = 256;
        int blocks = (int)((total + threads - 1) / threads);
        pull_kernel<<<blocks, threads>>>(x, out);
    }
}

// round 8
// speedup vs baseline: 1.4684x; 1.1166x over previous
#include <cuda_runtime.h>

#define N_NODES 100000
#define DIM 64
#define N_EDGES 1250000
#define CAP 64          // bucket slots per node; Poisson(12.5) max degree ~40

// Static scratch (zero-initialized at module load; pull re-zeroes g_cnt/g_novf
// after use so every graph replay starts from a clean state).
__device__ int g_cnt[N_NODES];                    // incoming-edge count per node
__device__ int g_bucket[(size_t)N_NODES * CAP];   // src ids, bucketed by dst
__device__ int g_novf;                            // overflow edge count (normally 0)
__device__ int g_ovf_src[N_EDGES];                // overflow edges (correctness path)
__device__ int g_ovf_dst[N_EDGES];

// 4 edges per thread (int4 loads): claim slots in dst buckets.
__global__ void fill_kernel(const int* __restrict__ edge_index) {
    int t = blockIdx.x * blockDim.x + threadIdx.x;
    if (t >= N_EDGES / 4) return;
    int4 s4 = reinterpret_cast<const int4*>(edge_index)[t];
    int4 d4 = reinterpret_cast<const int4*>(edge_index + N_EDGES)[t];
    int ss[4] = {s4.x, s4.y, s4.z, s4.w};
    int dd[4] = {d4.x, d4.y, d4.z, d4.w};
    #pragma unroll
    for (int k = 0; k < 4; k++) {
        int src = ss[k], dst = dd[k];
        int slot = atomicAdd(&g_cnt[dst], 1);
        if (slot < CAP) {
            g_bucket[(size_t)dst * CAP + slot] = src;
        } else {
            int q = atomicAdd(&g_novf, 1);
            if (q < N_EDGES) { g_ovf_src[q] = src; g_ovf_dst[q] = dst; }
        }
    }
}

// Warp per node. All lanes load the SAME int4 of bucket indices (warp-uniform
// broadcast, no shfl), then 4 independent row gathers (float2/lane = 256B row).
__global__ void pull_kernel(const float* __restrict__ x,
                            float* __restrict__ out) {
    int gtid = blockIdx.x * blockDim.x + threadIdx.x;
    int node = gtid >> 5;
    int lane = gtid & 31;
    if (node >= N_NODES) return;

    const unsigned FULL = 0xFFFFFFFFu;
    int cnt = g_cnt[node];                       // uniform broadcast load
    int m = cnt < CAP ? cnt : CAP;

    const int* bp = g_bucket + (size_t)node * CAP;          // 256B-aligned
    const float2* xb = reinterpret_cast<const float2*>(x) + lane;

    float accx0 = 0.f, accy0 = 0.f, accx1 = 0.f, accy1 = 0.f;

    int j = 0;
    for (; j + 4 <= m; j += 4) {
        int4 s = *reinterpret_cast<const int4*>(bp + j);    // uniform LDG.128
        float2 v0 = xb[(size_t)s.x * (DIM / 2)];
        float2 v1 = xb[(size_t)s.y * (DIM / 2)];
        float2 v2 = xb[(size_t)s.z * (DIM / 2)];
        float2 v3 = xb[(size_t)s.w * (DIM / 2)];
        accx0 += v0.x + v1.x;
        accy0 += v0.y + v1.y;
        accx1 += v2.x + v3.x;
        accy1 += v2.y + v3.y;
    }
    for (; j < m; j++) {
        int sj = bp[j];                                     // uniform LDG.32
        float2 v = xb[(size_t)sj * (DIM / 2)];
        accx0 += v.x;
        accy0 += v.y;
    }
    float accx = accx0 + accx1;
    float accy = accy0 + accy1;

    // Overflow correctness path (normally dead: g_novf == 0).
    if (cnt > CAP) {
        int no = g_novf;
        if (no > N_EDGES) no = N_EDGES;
        for (int k = 0; k < no; k++) {
            if (g_ovf_dst[k] == node) {
                int sj = g_ovf_src[k];
                float2 v = xb[(size_t)sj * (DIM / 2)];
                accx += v.x;
                accy += v.y;
            }
        }
    }

    // Reset state for the next graph replay (exclusive owner of this element).
    if (lane == 0) g_cnt[node] = 0;
    if (node == 0 && lane == 1) g_novf = 0;

    float inv_cnt = 1.0f / fmaxf((float)cnt, 1.0f);
    accx *= inv_cnt;
    accy *= inv_cnt;

    float ss = accx * accx + accy * accy;
    #pragma unroll
    for (int off = 16; off > 0; off >>= 1)
        ss += __shfl_xor_sync(FULL, ss, off);

    float scale = 2.0f / fmaxf(sqrtf(ss), 1e-12f);
    float2 r;
    r.x = fmaxf(accx * scale, 0.0f);
    r.y = fmaxf(accy * scale, 0.0f);
    reinterpret_cast<float2*>(out + (size_t)node * DIM)[lane] = r;
}

extern "C" void kernel_launch(void* const* d_in, const int* in_sizes, int n_in,
                              void* d_out, int out_size) {
    const float* x = (const float*)d_in[0];
    const int* edge_index = (const int*)d_in[1];
    // d_in[2] = edge_weights: unused by the reference computation.
    float* out = (float*)d_out;

    {
        int total = N_EDGES / 4;
        int threads = 256;
        int blocks = (total + threads - 1) / threads;
        fill_kernel<<<blocks, threads>>>(edge_index);
    }
    {
        long long total = (long long)N_NODES * 32;
        int threads = 256;
        int blocks = (int)((total + threads - 1) / threads);
        pull_kernel<<<blocks, threads>>>(x, out);
    }
}

// round 9
// speedup vs baseline: 1.4802x; 1.0080x over previous
#include <cuda_runtime.h>

#define N_NODES 100000
#define DIM 64
#define N_EDGES 1250000
#define CAP 64          // bucket slots per node; Poisson(12.5) max degree ~40

// Static scratch (zero-initialized at module load; pull re-zeroes g_cnt/g_novf
// after use so every graph replay starts from a clean state).
// +4 pad: the pipelined prefetch may read one int4 past the last bucket.
__device__ int g_cnt[N_NODES];
__device__ int g_bucket[(size_t)N_NODES * CAP + 4];
__device__ int g_novf;
__device__ int g_ovf_src[N_EDGES];
__device__ int g_ovf_dst[N_EDGES];

// 4 edges per thread (int4 loads): claim slots in dst buckets.
__global__ void fill_kernel(const int* __restrict__ edge_index) {
    int t = blockIdx.x * blockDim.x + threadIdx.x;
    if (t >= N_EDGES / 4) return;
    int4 s4 = reinterpret_cast<const int4*>(edge_index)[t];
    int4 d4 = reinterpret_cast<const int4*>(edge_index + N_EDGES)[t];
    int ss[4] = {s4.x, s4.y, s4.z, s4.w};
    int dd[4] = {d4.x, d4.y, d4.z, d4.w};
    #pragma unroll
    for (int k = 0; k < 4; k++) {
        int src = ss[k], dst = dd[k];
        int slot = atomicAdd(&g_cnt[dst], 1);
        if (slot < CAP) {
            g_bucket[(size_t)dst * CAP + slot] = src;
        } else {
            int q = atomicAdd(&g_novf, 1);
            if (q < N_EDGES) { g_ovf_src[q] = src; g_ovf_dst[q] = dst; }
        }
    }
}

// Warp per node. Pipelined uniform int4 index loads; 4 row-gathers in flight.
// Normalization is scale-invariant => the mean's 1/cnt cancels: out = relu(2*agg/||agg||).
__global__ void pull_kernel(const float* __restrict__ x,
                            float* __restrict__ out) {
    int gtid = blockIdx.x * blockDim.x + threadIdx.x;
    int node = gtid >> 5;
    int lane = gtid & 31;
    if (node >= N_NODES) return;

    const unsigned FULL = 0xFFFFFFFFu;
    int cnt = g_cnt[node];                        // uniform broadcast load
    int m = cnt < CAP ? cnt : CAP;

    const int* bp = g_bucket + (size_t)node * CAP;           // 256B-aligned
    const float2* xb = reinterpret_cast<const float2*>(x) + lane;

    float ax0 = 0.f, ay0 = 0.f, ax1 = 0.f, ay1 = 0.f;

    // Prefetch first index quad (values unused when m==0; memory always valid).
    int4 s = *reinterpret_cast<const int4*>(bp);
    int j = 0;
    for (; j + 4 <= m; j += 4) {
        int4 cur = s;
        s = *reinterpret_cast<const int4*>(bp + j + 4);      // prefetch next (pad keeps in-bounds)
        float2 v0 = xb[(size_t)cur.x * (DIM / 2)];
        float2 v1 = xb[(size_t)cur.y * (DIM / 2)];
        float2 v2 = xb[(size_t)cur.z * (DIM / 2)];
        float2 v3 = xb[(size_t)cur.w * (DIM / 2)];
        ax0 += v0.x + v1.x;
        ay0 += v0.y + v1.y;
        ax1 += v2.x + v3.x;
        ay1 += v2.y + v3.y;
    }
    // Tail (0..3 edges) uses the already-prefetched quad: no more index loads.
    int r = m - j;
    if (r > 0) { float2 v = xb[(size_t)s.x * (DIM / 2)]; ax0 += v.x; ay0 += v.y; }
    if (r > 1) { float2 v = xb[(size_t)s.y * (DIM / 2)]; ax1 += v.x; ay1 += v.y; }
    if (r > 2) { float2 v = xb[(size_t)s.z * (DIM / 2)]; ax0 += v.x; ay0 += v.y; }

    float accx = ax0 + ax1;
    float accy = ay0 + ay1;

    // Overflow correctness path (normally dead: g_novf == 0).
    if (cnt > CAP) {
        int no = g_novf;
        if (no > N_EDGES) no = N_EDGES;
        for (int k = 0; k < no; k++) {
            if (g_ovf_dst[k] == node) {
                int sj = g_ovf_src[k];
                float2 v = xb[(size_t)sj * (DIM / 2)];
                accx += v.x;
                accy += v.y;
            }
        }
    }

    // Reset state for the next graph replay (exclusive owner of this element).
    if (lane == 0) g_cnt[node] = 0;
    if (node == 0 && lane == 1) g_novf = 0;

    // ||agg|| reduce across the warp.
    float ss = accx * accx + accy * accy;
    #pragma unroll
    for (int off = 16; off > 0; off >>= 1)
        ss += __shfl_xor_sync(FULL, ss, off);

    // out = relu(2 * agg / ||agg||); 1/cnt cancels under normalization.
    // agg==0 -> acc*scale == 0 exactly (scale finite), matching reference.
    float scale = 2.0f * rsqrtf(fmaxf(ss, 1e-30f));
    float2 rr;
    rr.x = fmaxf(accx * scale, 0.0f);
    rr.y = fmaxf(accy * scale, 0.0f);
    reinterpret_cast<float2*>(out + (size_t)node * DIM)[lane] = rr;
}

extern "C" void kernel_launch(void* const* d_in, const int* in_sizes, int n_in,
                              void* d_out, int out_size) {
    const float* x = (const float*)d_in[0];
    const int* edge_index = (const int*)d_in[1];
    // d_in[2] = edge_weights: unused by the reference computation.
    float* out = (float*)d_out;

    {
        int total = N_EDGES / 4;
        int threads = 256;
        int blocks = (total + threads - 1) / threads;
        fill_kernel<<<blocks, threads>>>(edge_index);
    }
    {
        long long total = (long long)N_NODES * 32;
        int threads = 256;
        int blocks = (int)((total + threads - 1) / threads);
        pull_kernel<<<blocks, threads>>>(x, out);
    }
}

// round 11
// speedup vs baseline: 1.5412x; 1.0412x over previous
#include <cuda_runtime.h>

#define N_NODES 100000
#define DIM 64
#define N_EDGES 1250000
#define CAP 64          // bucket slots per node; Poisson(12.5) max degree ~40

// Static scratch (zero-initialized at module load; pull re-zeroes g_cnt/g_novf
// after use so every graph replay starts from a clean state).
// +8 pad: pipelined prefetch may read up to two int4 past the last bucket.
__device__ int g_cnt[N_NODES];
__device__ int g_bucket[(size_t)N_NODES * CAP + 8];
__device__ int g_novf;
__device__ int g_ovf_src[N_EDGES];
__device__ int g_ovf_dst[N_EDGES];

// Packed fp32x2 add (Blackwell): one instruction, rn per component (bit-exact
// vs two scalar FADDs).
__device__ __forceinline__ void fadd2(unsigned long long& a, unsigned long long v) {
    asm("add.rn.f32x2 %0, %0, %1;" : "+l"(a) : "l"(v));
}

// 4 edges per thread (int4 loads): claim slots in dst buckets.
__global__ void fill_kernel(const int* __restrict__ edge_index) {
    int t = blockIdx.x * blockDim.x + threadIdx.x;
    if (t >= N_EDGES / 4) return;
    int4 s4 = reinterpret_cast<const int4*>(edge_index)[t];
    int4 d4 = reinterpret_cast<const int4*>(edge_index + N_EDGES)[t];
    int ss[4] = {s4.x, s4.y, s4.z, s4.w};
    int dd[4] = {d4.x, d4.y, d4.z, d4.w};
    #pragma unroll
    for (int k = 0; k < 4; k++) {
        int src = ss[k], dst = dd[k];
        int slot = atomicAdd(&g_cnt[dst], 1);
        if (slot < CAP) {
            g_bucket[(size_t)dst * CAP + slot] = src;
        } else {
            int q = atomicAdd(&g_novf, 1);
            if (q < N_EDGES) { g_ovf_src[q] = src; g_ovf_dst[q] = dst; }
        }
    }
}

// Warp per node. Uniform (broadcast) index quads, 8 gathers in flight on the
// main path, packed f32x2 accumulation. out = relu(2*agg/||agg||) — the mean's
// 1/cnt cancels under normalization.
__global__ void pull_kernel(const float* __restrict__ x,
                            float* __restrict__ out) {
    int gtid = blockIdx.x * blockDim.x + threadIdx.x;
    int node = gtid >> 5;
    int lane = gtid & 31;
    if (node >= N_NODES) return;

    const unsigned FULL = 0xFFFFFFFFu;
    int cnt = g_cnt[node];                         // uniform broadcast load
    int m = cnt < CAP ? cnt : CAP;

    const int* bp = g_bucket + (size_t)node * CAP; // 256B-aligned
    const unsigned long long* xb =
        reinterpret_cast<const unsigned long long*>(x) + lane;  // lane's float2 column

    unsigned long long a0 = 0, a1 = 0, a2 = 0, a3 = 0;  // packed {0.f,0.f}

    int4 s = *reinterpret_cast<const int4*>(bp);   // prefetched quad (always valid)
    int j = 0;

    // 8-edge body: two quads, 8 independent gathers in flight.
    for (; j + 8 <= m; j += 8) {
        int4 q0 = s;
        int4 q1 = *reinterpret_cast<const int4*>(bp + j + 4);
        s = *reinterpret_cast<const int4*>(bp + j + 8);      // prefetch (pad-safe)
        unsigned long long v0 = xb[(size_t)q0.x * (DIM / 2)];
        unsigned long long v1 = xb[(size_t)q0.y * (DIM / 2)];
        unsigned long long v2 = xb[(size_t)q0.z * (DIM / 2)];
        unsigned long long v3 = xb[(size_t)q0.w * (DIM / 2)];
        unsigned long long v4 = xb[(size_t)q1.x * (DIM / 2)];
        unsigned long long v5 = xb[(size_t)q1.y * (DIM / 2)];
        unsigned long long v6 = xb[(size_t)q1.z * (DIM / 2)];
        unsigned long long v7 = xb[(size_t)q1.w * (DIM / 2)];
        fadd2(a0, v0); fadd2(a1, v1); fadd2(a2, v2); fadd2(a3, v3);
        fadd2(a0, v4); fadd2(a1, v5); fadd2(a2, v6); fadd2(a3, v7);
    }
    // 4-edge body.
    for (; j + 4 <= m; j += 4) {
        int4 cur = s;
        s = *reinterpret_cast<const int4*>(bp + j + 4);      // prefetch (pad-safe)
        unsigned long long v0 = xb[(size_t)cur.x * (DIM / 2)];
        unsigned long long v1 = xb[(size_t)cur.y * (DIM / 2)];
        unsigned long long v2 = xb[(size_t)cur.z * (DIM / 2)];
        unsigned long long v3 = xb[(size_t)cur.w * (DIM / 2)];
        fadd2(a0, v0); fadd2(a1, v1); fadd2(a2, v2); fadd2(a3, v3);
    }
    // Tail (0..3): uses the already-prefetched quad, no further index loads.
    int r = m - j;
    if (r > 0) fadd2(a0, xb[(size_t)s.x * (DIM / 2)]);
    if (r > 1) fadd2(a1, xb[(size_t)s.y * (DIM / 2)]);
    if (r > 2) fadd2(a2, xb[(size_t)s.z * (DIM / 2)]);

    fadd2(a0, a1); fadd2(a2, a3); fadd2(a0, a2);
    float2 acc = *reinterpret_cast<float2*>(&a0);
    float accx = acc.x, accy = acc.y;

    // Overflow correctness path (normally dead: g_novf == 0).
    if (cnt > CAP) {
        int no = g_novf;
        if (no > N_EDGES) no = N_EDGES;
        for (int k = 0; k < no; k++) {
            if (g_ovf_dst[k] == node) {
                unsigned long long v = xb[(size_t)g_ovf_src[k] * (DIM / 2)];
                float2 f = *reinterpret_cast<float2*>(&v);
                accx += f.x;
                accy += f.y;
            }
        }
    }

    // Reset state for the next graph replay (exclusive owner of this element).
    if (lane == 0) g_cnt[node] = 0;
    if (node == 0 && lane == 1) g_novf = 0;

    // ||agg|| reduce across the warp.
    float ss2 = accx * accx + accy * accy;
    #pragma unroll
    for (int off = 16; off > 0; off >>= 1)
        ss2 += __shfl_xor_sync(FULL, ss2, off);

    // out = relu(2 * agg / ||agg||). agg==0 -> 0 exactly, matching reference.
    float scale = 2.0f * rsqrtf(fmaxf(ss2, 1e-30f));
    float2 rr;
    rr.x = fmaxf(accx * scale, 0.0f);
    rr.y = fmaxf(accy * scale, 0.0f);
    reinterpret_cast<float2*>(out + (size_t)node * DIM)[lane] = rr;
}

extern "C" void kernel_launch(void* const* d_in, const int* in_sizes, int n_in,
                              void* d_out, int out_size) {
    const float* x = (const float*)d_in[0];
    const int* edge_index = (const int*)d_in[1];
    // d_in[2] = edge_weights: unused by the reference computation.
    float* out = (float*)d_out;

    {
        int total = N_EDGES / 4;
        int threads = 256;
        int blocks = (total + threads - 1) / threads;
        fill_kernel<<<blocks, threads>>>(edge_index);
    }
    {
        long long total = (long long)N_NODES * 32;
        int threads = 256;
        int blocks = (int)((total + threads - 1) / threads);
        pull_kernel<<<blocks, threads>>>(x, out);
    }
}